// round 1
// baseline (speedup 1.0000x reference)
#include <cuda_runtime.h>
#include <cuda_bf16.h>
#include <math.h>

// ---------------------------------------------------------------------------
// MP_Layer: GNN message-passing layer, fp32 baseline.
//   B=16, N=128, D=S=128, MP_INT=UP_INT=256.
// Pipeline:
//   K_pre : Pi_a/Pj_a/Pi_m/Pj_m/Pu = nodes @ W1x[slice]      (tiny GEMMs)
//   K_edge: per (b,p) tile of 128 edges:
//             H1 = relu(E @ W1a[256:384] + Pi_a[q] + Pj_a[p] + b1a)
//             NE = relu(H1 @ W2a + b2a) * mask
//             edges_out = BN_e(NE)
//             H2 = relu(NE @ W1m[256:384] + Pi_m[q] + Pj_m[p] + b1m)
//             MSG = relu(H2 @ W2m + b2m) * mask
//             agg[b,p] = sum_q MSG            (in-block reduction, no atomics)
//   K_node: s = relu(relu(Pu + agg @ W1u[128:256] + b1u) @ W2u + b2u)
//           nodes_out = BN_n(s)
// ---------------------------------------------------------------------------

#define EPSBN 1e-3f

static const int Bb = 16;
static const int Nn = 128;
static const int Dd = 128;

// scratch (device globals; no allocation allowed)
__device__ __align__(16) float g_Pi_a[2048 * 256];
__device__ __align__(16) float g_Pj_a[2048 * 256];
__device__ __align__(16) float g_Pi_m[2048 * 256];
__device__ __align__(16) float g_Pj_m[2048 * 256];
__device__ __align__(16) float g_Pu [2048 * 256];
__device__ __align__(16) float g_agg[2048 * 128];

// XOR swizzle for transposed activation buffers: element (a=k, b=row)
// bank = (b ^ (((a>>3)&3)<<3)) mod 32 spreads column-stores across banks.
__device__ __forceinline__ int SWZ(int a, int b) {
    return a * 128 + (b ^ (((a >> 3) & 3) << 3));
}

// ---------------------------------------------------------------------------
// Generic 128xNcolsxK GEMM tile: C[128][128] (one 128-col slab),
// A^T in swizzled smem, W streamed from global via sW chunks.
// Each thread owns an 8x8 micro-tile: rows row0..row0+7, cols col0..col0+7.
// ---------------------------------------------------------------------------
__device__ __forceinline__ void gemm_tile(
    const float* __restrict__ sA,      // swizzled A^T, K x 128
    float* __restrict__ sW,            // [32][132] staging
    const float* __restrict__ gW0,     // global W, already offset to (row0=0, col=ncb)
    int ldw, int K,
    int tid, int row0, int col0,
    float (&acc)[8][8])
{
    for (int kb = 0; kb < K; kb += 32) {
        __syncthreads();
        // stage 32x128 weight chunk (1024 float4, 4 per thread, coalesced)
        #pragma unroll
        for (int i = 0; i < 4; i++) {
            int f4 = tid + (i << 8);
            int rr = f4 >> 5;
            int cc = (f4 & 31) << 2;
            *(float4*)(sW + rr * 132 + cc) =
                *(const float4*)(gW0 + (size_t)(kb + rr) * ldw + cc);
        }
        __syncthreads();
        #pragma unroll 4
        for (int kk = 0; kk < 32; kk++) {
            int k = kb + kk;
            int xk = ((k >> 3) & 3) << 3;
            const float4* ap = (const float4*)(sA + k * 128 + (row0 ^ xk));
            float4 a0 = ap[0], a1 = ap[1];
            const float4* bp = (const float4*)(sW + kk * 132 + col0);
            float4 b0 = bp[0], b1 = bp[1];
            float av[8] = {a0.x, a0.y, a0.z, a0.w, a1.x, a1.y, a1.z, a1.w};
            float bv[8] = {b0.x, b0.y, b0.z, b0.w, b1.x, b1.y, b1.z, b1.w};
            #pragma unroll
            for (int i = 0; i < 8; i++)
                #pragma unroll
                for (int j = 0; j < 8; j++)
                    acc[i][j] += av[i] * bv[j];
        }
    }
}

// store this thread's 8x8 (already activated) into swizzled dst at columns
// c = ncb+col0+j, rows row0..row0+7
__device__ __forceinline__ void store_tileT(
    float* __restrict__ sDst, int ncb, int row0, int col0, const float (&v)[8][8])
{
    #pragma unroll
    for (int j = 0; j < 8; j++) {
        int c  = ncb + col0 + j;
        int xc = ((c >> 3) & 3) << 3;
        float* d = sDst + c * 128 + (row0 ^ xc);
        float4 lo = make_float4(v[0][j], v[1][j], v[2][j], v[3][j]);
        float4 hi = make_float4(v[4][j], v[5][j], v[6][j], v[7][j]);
        *(float4*)(d)     = lo;
        *(float4*)(d + 4) = hi;
    }
}

// ---------------------------------------------------------------------------
// Kernel A: node precompute. Block = 16 node rows.
// ---------------------------------------------------------------------------
__global__ __launch_bounds__(256) void precompute_kernel(
    const float* __restrict__ nodes,
    const float* __restrict__ W1a,
    const float* __restrict__ W1m,
    const float* __restrict__ W1u)
{
    __shared__ float sX[16 * 128];
    int row0 = blockIdx.x * 16;
    int tid = threadIdx.x;
    for (int idx = tid; idx < 2048; idx += 256)
        sX[idx] = nodes[(size_t)row0 * 128 + idx];
    __syncthreads();

    const float* Ws[5] = {W1a, W1a + 128 * 256, W1m, W1m + 128 * 256, W1u};
    float* Os[5] = {g_Pi_a, g_Pj_a, g_Pi_m, g_Pj_m, g_Pu};

    #pragma unroll 1
    for (int m = 0; m < 5; m++) {
        const float* W = Ws[m] + tid;   // col = tid (0..255)
        float a[16];
        #pragma unroll
        for (int r = 0; r < 16; r++) a[r] = 0.f;
        #pragma unroll 2
        for (int kb = 0; kb < 128; kb += 4) {
            float w0 = W[(size_t)(kb + 0) * 256];
            float w1 = W[(size_t)(kb + 1) * 256];
            float w2 = W[(size_t)(kb + 2) * 256];
            float w3 = W[(size_t)(kb + 3) * 256];
            #pragma unroll
            for (int r = 0; r < 16; r++) {
                float4 xv = *(const float4*)(sX + r * 128 + kb);
                a[r] += xv.x * w0 + xv.y * w1 + xv.z * w2 + xv.w * w3;
            }
        }
        float* O = Os[m] + (size_t)row0 * 256 + tid;
        #pragma unroll
        for (int r = 0; r < 16; r++) O[(size_t)r * 256] = a[r];
    }
}

// ---------------------------------------------------------------------------
// Kernel B: fused edge pipeline. Block = one (b, p) row of 128 edges.
// smem: sE (swz 128x128) | sH (swz 256x128) | sW [32][132] (alias sRed) | sMask[128]
// ---------------------------------------------------------------------------
#define SM_E 0
#define SM_H 16384
#define SM_W 49152
#define SM_M 53376
#define SMEM_B_FLOATS 53504  // 214016 bytes

__global__ __launch_bounds__(256, 1) void edge_kernel(
    const float* __restrict__ edges, const float* __restrict__ mask,
    const float* __restrict__ W1a, const float* __restrict__ b1a,
    const float* __restrict__ W2a, const float* __restrict__ b2a,
    const float* __restrict__ W1m, const float* __restrict__ b1m,
    const float* __restrict__ W2m, const float* __restrict__ b2m,
    const float* __restrict__ gamma_e, const float* __restrict__ beta_e,
    const float* __restrict__ mean_e,  const float* __restrict__ var_e,
    float* __restrict__ edges_out)
{
    extern __shared__ float sm[];
    float* sE = sm + SM_E;
    float* sH = sm + SM_H;
    float* sW = sm + SM_W;
    float* sMask = sm + SM_M;
    float* sRed = sW;  // alias (used only after last GEMM, with sync)

    int p  = blockIdx.x;
    int bb = blockIdx.y;
    int tid = threadIdx.x;
    int ty = tid >> 4, tx = tid & 15;
    int row0 = ty * 8, col0 = tx * 8;

    // load edge tile transposed+swizzled
    const float* Eg = edges + ((size_t)bb * 16384 + (size_t)p * 128) * 128;
    for (int idx = tid; idx < 16384; idx += 256) {
        int r = idx >> 7, k = idx & 127;
        sE[SWZ(k, r)] = Eg[idx];
    }
    if (tid < 128) sMask[tid] = mask[(size_t)bb * 16384 + p * 128 + tid];

    float acc[8][8];

    // ---- GEMM1: H1 = relu(E @ W1a_e + Pi_a[q] + Pj_a[p] + b1a) -> sH
    #pragma unroll 1
    for (int h = 0; h < 2; h++) {
        int ncb = h * 128;
        #pragma unroll
        for (int i = 0; i < 8; i++)
            #pragma unroll
            for (int j = 0; j < 8; j++) acc[i][j] = 0.f;
        gemm_tile(sE, sW, W1a + (size_t)256 * 256 + ncb, 256, 128, tid, row0, col0, acc);
        float bj[8];
        {
            const float* Pj = g_Pj_a + ((size_t)(bb * 128 + p)) * 256 + ncb + col0;
            #pragma unroll
            for (int j = 0; j < 8; j++) bj[j] = b1a[ncb + col0 + j] + Pj[j];
        }
        const float* Pi = g_Pi_a + ((size_t)bb * 128) * 256 + ncb + col0;
        #pragma unroll
        for (int i = 0; i < 8; i++) {
            const float* pir = Pi + (size_t)(row0 + i) * 256;
            float4 p0 = *(const float4*)(pir);
            float4 p1 = *(const float4*)(pir + 4);
            float pv[8] = {p0.x, p0.y, p0.z, p0.w, p1.x, p1.y, p1.z, p1.w};
            #pragma unroll
            for (int j = 0; j < 8; j++) {
                float v = acc[i][j] + pv[j] + bj[j];
                acc[i][j] = fmaxf(v, 0.f);
            }
        }
        store_tileT(sH, ncb, row0, col0, acc);
    }

    // ---- GEMM2: NE = relu(H1 @ W2a + b2a) * mask ; edges_out = BN(NE); NE -> sE
    #pragma unroll
    for (int i = 0; i < 8; i++)
        #pragma unroll
        for (int j = 0; j < 8; j++) acc[i][j] = 0.f;
    gemm_tile(sH, sW, W2a, 128, 256, tid, row0, col0, acc);
    {
        float bj[8], scl[8], shf[8];
        #pragma unroll
        for (int j = 0; j < 8; j++) {
            int c = col0 + j;
            bj[j]  = b2a[c];
            float s = gamma_e[c] * rsqrtf(var_e[c] + EPSBN);
            scl[j] = s;
            shf[j] = beta_e[c] - mean_e[c] * s;
        }
        #pragma unroll
        for (int i = 0; i < 8; i++) {
            int r = row0 + i;
            float mv = sMask[r];
            float* go = edges_out + (((size_t)bb * 16384) + (size_t)p * 128 + r) * 128 + col0;
            float ov[8];
            #pragma unroll
            for (int j = 0; j < 8; j++) {
                float v = fmaxf(acc[i][j] + bj[j], 0.f) * mv;
                acc[i][j] = v;
                ov[j] = v * scl[j] + shf[j];
            }
            *(float4*)(go)     = make_float4(ov[0], ov[1], ov[2], ov[3]);
            *(float4*)(go + 4) = make_float4(ov[4], ov[5], ov[6], ov[7]);
        }
        store_tileT(sE, 0, row0, col0, acc);
    }

    // ---- GEMM3: H2 = relu(NE @ W1m_e + Pi_m[q] + Pj_m[p] + b1m) -> sH
    #pragma unroll 1
    for (int h = 0; h < 2; h++) {
        int ncb = h * 128;
        #pragma unroll
        for (int i = 0; i < 8; i++)
            #pragma unroll
            for (int j = 0; j < 8; j++) acc[i][j] = 0.f;
        gemm_tile(sE, sW, W1m + (size_t)256 * 256 + ncb, 256, 128, tid, row0, col0, acc);
        float bj[8];
        {
            const float* Pj = g_Pj_m + ((size_t)(bb * 128 + p)) * 256 + ncb + col0;
            #pragma unroll
            for (int j = 0; j < 8; j++) bj[j] = b1m[ncb + col0 + j] + Pj[j];
        }
        const float* Pi = g_Pi_m + ((size_t)bb * 128) * 256 + ncb + col0;
        #pragma unroll
        for (int i = 0; i < 8; i++) {
            const float* pir = Pi + (size_t)(row0 + i) * 256;
            float4 p0 = *(const float4*)(pir);
            float4 p1 = *(const float4*)(pir + 4);
            float pv[8] = {p0.x, p0.y, p0.z, p0.w, p1.x, p1.y, p1.z, p1.w};
            #pragma unroll
            for (int j = 0; j < 8; j++) {
                float v = acc[i][j] + pv[j] + bj[j];
                acc[i][j] = fmaxf(v, 0.f);
            }
        }
        store_tileT(sH, ncb, row0, col0, acc);
    }

    // ---- GEMM4: MSG = relu(H2 @ W2m + b2m) * mask ; agg = sum over rows(q)
    #pragma unroll
    for (int i = 0; i < 8; i++)
        #pragma unroll
        for (int j = 0; j < 8; j++) acc[i][j] = 0.f;
    gemm_tile(sH, sW, W2m, 128, 256, tid, row0, col0, acc);
    {
        float bj[8], csum[8];
        #pragma unroll
        for (int j = 0; j < 8; j++) { bj[j] = b2m[col0 + j]; csum[j] = 0.f; }
        #pragma unroll
        for (int i = 0; i < 8; i++) {
            float mv = sMask[row0 + i];
            #pragma unroll
            for (int j = 0; j < 8; j++)
                csum[j] += fmaxf(acc[i][j] + bj[j], 0.f) * mv;
        }
        __syncthreads();  // all GEMM4 reads of sW done before aliasing as sRed
        #pragma unroll
        for (int j = 0; j < 8; j++)
            sRed[ty * 128 + col0 + j] = csum[j];
        __syncthreads();
        if (tid < 128) {
            float s = 0.f;
            #pragma unroll
            for (int t = 0; t < 16; t++) s += sRed[t * 128 + tid];
            g_agg[((size_t)bb * 128 + p) * 128 + tid] = s;
        }
    }
}

// ---------------------------------------------------------------------------
// Kernel C: node update + BN. Block = 16 node rows.
// ---------------------------------------------------------------------------
__global__ __launch_bounds__(256) void node_kernel(
    const float* __restrict__ W1u, const float* __restrict__ b1u,
    const float* __restrict__ W2u, const float* __restrict__ b2u,
    const float* __restrict__ gamma_n, const float* __restrict__ beta_n,
    const float* __restrict__ mean_n,  const float* __restrict__ var_n,
    float* __restrict__ nodes_out)
{
    __shared__ float sA[16 * 128];
    __shared__ float sH2[16 * 256];
    int row0 = blockIdx.x * 16;
    int tid = threadIdx.x;

    for (int idx = tid; idx < 2048; idx += 256)
        sA[idx] = g_agg[(size_t)row0 * 128 + idx];
    __syncthreads();

    // phase 1: h[r][col] over 256 cols (col = tid)
    {
        float a[16];
        #pragma unroll
        for (int r = 0; r < 16; r++) a[r] = 0.f;
        const float* W = W1u + (size_t)128 * 256 + tid;
        #pragma unroll 2
        for (int kb = 0; kb < 128; kb += 4) {
            float w0 = W[(size_t)(kb + 0) * 256];
            float w1 = W[(size_t)(kb + 1) * 256];
            float w2 = W[(size_t)(kb + 2) * 256];
            float w3 = W[(size_t)(kb + 3) * 256];
            #pragma unroll
            for (int r = 0; r < 16; r++) {
                float4 xv = *(const float4*)(sA + r * 128 + kb);
                a[r] += xv.x * w0 + xv.y * w1 + xv.z * w2 + xv.w * w3;
            }
        }
        float bb1 = b1u[tid];
        #pragma unroll
        for (int r = 0; r < 16; r++) {
            float v = a[r] + g_Pu[(size_t)(row0 + r) * 256 + tid] + bb1;
            sH2[r * 256 + tid] = fmaxf(v, 0.f);
        }
    }
    __syncthreads();

    // phase 2: s[r][col] over 128 cols; thread handles 8 rows
    {
        int col = tid & 127;
        int rh  = tid >> 7;   // 0 or 1 -> rows rh*8 .. rh*8+7
        float c8[8];
        #pragma unroll
        for (int rr = 0; rr < 8; rr++) c8[rr] = 0.f;
        const float* W2 = W2u + col;
        #pragma unroll 2
        for (int kb = 0; kb < 256; kb += 4) {
            float w0 = W2[(size_t)(kb + 0) * 128];
            float w1 = W2[(size_t)(kb + 1) * 128];
            float w2 = W2[(size_t)(kb + 2) * 128];
            float w3 = W2[(size_t)(kb + 3) * 128];
            #pragma unroll
            for (int rr = 0; rr < 8; rr++) {
                float4 hv = *(const float4*)(sH2 + (rh * 8 + rr) * 256 + kb);
                c8[rr] += hv.x * w0 + hv.y * w1 + hv.z * w2 + hv.w * w3;
            }
        }
        float bb2 = b2u[col];
        float s = gamma_n[col] * rsqrtf(var_n[col] + EPSBN);
        float sh = beta_n[col] - mean_n[col] * s;
        #pragma unroll
        for (int rr = 0; rr < 8; rr++) {
            float v = fmaxf(c8[rr] + bb2, 0.f);
            nodes_out[(size_t)(row0 + rh * 8 + rr) * 128 + col] = v * s + sh;
        }
    }
}

// ---------------------------------------------------------------------------
extern "C" void kernel_launch(void* const* d_in, const int* in_sizes, int n_in,
                              void* d_out, int out_size)
{
    const float* nodes = (const float*)d_in[0];
    const float* edges = (const float*)d_in[1];
    const float* mask  = (const float*)d_in[2];
    const float* W1a = (const float*)d_in[3];
    const float* b1a = (const float*)d_in[4];
    const float* W2a = (const float*)d_in[5];
    const float* b2a = (const float*)d_in[6];
    const float* W1m = (const float*)d_in[7];
    const float* b1m = (const float*)d_in[8];
    const float* W2m = (const float*)d_in[9];
    const float* b2m = (const float*)d_in[10];
    const float* W1u = (const float*)d_in[11];
    const float* b1u = (const float*)d_in[12];
    const float* W2u = (const float*)d_in[13];
    const float* b2u = (const float*)d_in[14];
    const float* gamma_n = (const float*)d_in[15];
    const float* beta_n  = (const float*)d_in[16];
    const float* mean_n  = (const float*)d_in[17];
    const float* var_n   = (const float*)d_in[18];
    const float* gamma_e = (const float*)d_in[19];
    const float* beta_e  = (const float*)d_in[20];
    const float* mean_e  = (const float*)d_in[21];
    const float* var_e   = (const float*)d_in[22];

    float* out = (float*)d_out;
    float* nodes_out = out;                      // (16, 128, 128)
    float* edges_out = out + (size_t)Bb * Nn * Dd;  // (16, 16384, 128)

    static const size_t smemB = SMEM_B_FLOATS * sizeof(float);
    cudaFuncSetAttribute(edge_kernel, cudaFuncAttributeMaxDynamicSharedMemorySize,
                         (int)smemB);

    precompute_kernel<<<128, 256>>>(nodes, W1a, W1m, W1u);

    dim3 gridB(Nn, Bb);
    edge_kernel<<<gridB, 256, smemB>>>(edges, mask,
                                       W1a, b1a, W2a, b2a,
                                       W1m, b1m, W2m, b2m,
                                       gamma_e, beta_e, mean_e, var_e,
                                       edges_out);

    node_kernel<<<128, 256>>>(W1u, b1u, W2u, b2u,
                              gamma_n, beta_n, mean_n, var_n,
                              nodes_out);
}